// round 3
// baseline (speedup 1.0000x reference)
#include <cuda_runtime.h>
#include <math.h>

namespace lsgm {

constexpr int nB   = 4;
constexpr int nT   = 4096;
constexpr int nDIM = 1024;
constexpr int nHID = 1536;
constexpr int nHID2 = 3072;
constexpr int nS   = 16;
constexpr int nD   = 384;
constexpr int nL   = 256;
constexpr int nM   = nB * nT;       // 16384
constexpr int CH   = 64;            // scan chunk length
constexpr int NG   = nT / CH;       // 64 chunks

constexpr float INV_SQRT_D = 0.05103103630798287f;   // 1/sqrt(384)

// ---------------- scratch (static device globals; no runtime alloc) ----------------
__device__ float g_proj [(size_t)nM * nHID2];   // [M,3072]  gate | xh0
__device__ float g_xh1  [(size_t)nM * nHID];    // conv out
__device__ float g_gbuf [(size_t)nM * nHID2];   // gates GEMM out: forget | inp
__device__ float g_alpha[(size_t)nM * nHID];
__device__ float g_xh2  [(size_t)nM * nHID];    // scan input
__device__ float g_hbuf [(size_t)nM * nHID];    // scan output
__device__ float g_xh3  [(size_t)nM * nHID];    // silu(gate)*xh2
__device__ float g_xr   [(size_t)nM * nHID];    // gelu(xh3)*h
__device__ float g_rq   [(size_t)nM * nD];
__device__ float g_outg [(size_t)nM * nHID];
__device__ float g_qk   [nM];
__device__ float g_xg   [nM];
__device__ float g_q    [nS * nD];
__device__ float g_qw   [nS * nHID];
__device__ float g_u    [nB * nS * nHID];
__device__ float g_mem  [nB * nS * nD];
__device__ float g_rk   [nB * nS * nD];
__device__ float g_rv   [nB * nS * nHID];
__device__ float g_cA   [nB * NG * nHID];
__device__ float g_cB   [nB * NG * nHID];
__device__ float g_carry[nB * NG * nHID];

// ---------------- generic fp32 NT GEMM: C[M,N] = A[M,K] * B[N,K]^T (+bias[n]) ------
// BM=BN=128, BK=16, 256 threads, 8x8 microtile. All dims divisible (M%128, N%128, K%16).
__global__ __launch_bounds__(256) void sgemm_nt(
    const float* __restrict__ A, const float* __restrict__ B,
    const float* __restrict__ bias, float* __restrict__ C,
    int M, int N, int Kd)
{
    constexpr int BK = 16;
    __shared__ float As[BK][128];
    __shared__ float Bs[BK][128];
    const int tid = threadIdx.x;
    const int bm = blockIdx.y << 7;
    const int bn = blockIdx.x << 7;
    const int tx = tid & 15;   // N direction
    const int ty = tid >> 4;   // M direction
    float acc[8][8];
#pragma unroll
    for (int i = 0; i < 8; i++)
#pragma unroll
        for (int j = 0; j < 8; j++) acc[i][j] = 0.f;

    const int lr0 = tid >> 2;          // 0..63
    const int lr1 = lr0 + 64;          // 64..127
    const int lc  = (tid & 3) << 2;    // 0,4,8,12
    const float* Ap = A + (size_t)bm * Kd + lc;
    const float* Bp = B + (size_t)bn * Kd + lc;

    for (int k0 = 0; k0 < Kd; k0 += BK) {
        float4 a0 = *(const float4*)(Ap + (size_t)lr0 * Kd + k0);
        float4 a1 = *(const float4*)(Ap + (size_t)lr1 * Kd + k0);
        float4 b0 = *(const float4*)(Bp + (size_t)lr0 * Kd + k0);
        float4 b1 = *(const float4*)(Bp + (size_t)lr1 * Kd + k0);
        As[lc + 0][lr0] = a0.x; As[lc + 1][lr0] = a0.y; As[lc + 2][lr0] = a0.z; As[lc + 3][lr0] = a0.w;
        As[lc + 0][lr1] = a1.x; As[lc + 1][lr1] = a1.y; As[lc + 2][lr1] = a1.z; As[lc + 3][lr1] = a1.w;
        Bs[lc + 0][lr0] = b0.x; Bs[lc + 1][lr0] = b0.y; Bs[lc + 2][lr0] = b0.z; Bs[lc + 3][lr0] = b0.w;
        Bs[lc + 0][lr1] = b1.x; Bs[lc + 1][lr1] = b1.y; Bs[lc + 2][lr1] = b1.z; Bs[lc + 3][lr1] = b1.w;
        __syncthreads();
#pragma unroll
        for (int k = 0; k < BK; k++) {
            float4 av0 = *(const float4*)(&As[k][ty << 3]);
            float4 av1 = *(const float4*)(&As[k][(ty << 3) + 4]);
            float4 bv0 = *(const float4*)(&Bs[k][tx << 3]);
            float4 bv1 = *(const float4*)(&Bs[k][(tx << 3) + 4]);
            float av[8] = {av0.x, av0.y, av0.z, av0.w, av1.x, av1.y, av1.z, av1.w};
            float bv[8] = {bv0.x, bv0.y, bv0.z, bv0.w, bv1.x, bv1.y, bv1.z, bv1.w};
#pragma unroll
            for (int i = 0; i < 8; i++)
#pragma unroll
                for (int j = 0; j < 8; j++)
                    acc[i][j] += av[i] * bv[j];
        }
        __syncthreads();
    }
    float bb[8];
#pragma unroll
    for (int j = 0; j < 8; j++) bb[j] = bias ? bias[bn + (tx << 3) + j] : 0.f;
#pragma unroll
    for (int i = 0; i < 8; i++) {
        float* cp = C + (size_t)(bm + (ty << 3) + i) * N + bn + (tx << 3);
        float4 o0, o1;
        o0.x = acc[i][0] + bb[0]; o0.y = acc[i][1] + bb[1];
        o0.z = acc[i][2] + bb[2]; o0.w = acc[i][3] + bb[3];
        o1.x = acc[i][4] + bb[4]; o1.y = acc[i][5] + bb[5];
        o1.z = acc[i][6] + bb[6]; o1.w = acc[i][7] + bb[7];
        *(float4*)cp = o0;
        *(float4*)(cp + 4) = o1;
    }
}

// ------------- q = memory_slots @ wq_w^T  ([16,384]) -------------
__global__ void k_qproj(const float* __restrict__ ms, const float* __restrict__ wq)
{
    int n = blockIdx.x * blockDim.x + threadIdx.x;
    if (n >= nS * nD) return;
    int s = n / nD, d = n % nD;
    const float* mp = ms + (size_t)s * nD;
    const float* wp = wq + (size_t)d * nD;
    float a = 0.f;
#pragma unroll 4
    for (int e = 0; e < nD; e++) a += mp[e] * wp[e];
    g_q[n] = a;
}

// ------------- qw[s,h] = sum_d q[s,d]*wk_w[d,h]  ([16,1536]) -------------
__global__ void k_qwproj(const float* __restrict__ wk)
{
    int n = blockIdx.x * blockDim.x + threadIdx.x;
    if (n >= nS * nHID) return;
    int s = n / nHID, h = n % nHID;
    float a = 0.f;
#pragma unroll 4
    for (int d = 0; d < nD; d++) a += g_q[s * nD + d] * wk[(size_t)d * nHID + h];
    g_qw[n] = a;
}

// ------------- causal depthwise conv K=4 over xh0 = proj[:,HID:] -------------
__global__ void k_conv(const float* __restrict__ cw, const float* __restrict__ cb)
{
    int i = blockIdx.x * blockDim.x + threadIdx.x;
    if (i >= nM * nHID) return;
    int m = i / nHID;
    int h = i - m * nHID;
    int t = m & (nT - 1);
    const float* p = g_proj + (size_t)m * nHID2 + nHID + h;
    float w0 = cw[h * 4 + 0], w1 = cw[h * 4 + 1], w2 = cw[h * 4 + 2], w3 = cw[h * 4 + 3];
    float acc = cb[h] + w3 * p[0];
    if (t >= 1) acc += w2 * p[-(size_t)nHID2];
    if (t >= 2) acc += w1 * p[-(size_t)2 * nHID2];
    if (t >= 3) acc += w0 * p[-(size_t)3 * nHID2];
    g_xh1[i] = acc;
}

// ------------- alpha / scan input -------------
__global__ void k_alpha(const float* __restrict__ fb)
{
    int i = blockIdx.x * blockDim.x + threadIdx.x;
    if (i >= nM * nHID) return;
    int m = i / nHID;
    int h = i - m * nHID;
    float f  = g_gbuf[(size_t)m * nHID2 + h];
    float ip = g_gbuf[(size_t)m * nHID2 + nHID + h];
    float c  = -8.f * log1pf(expf(fb[h]));          // -8*softplus(forget_base)
    float sf = 1.f / (1.f + expf(-f));
    float a  = expf(c * sf);
    float si = 1.f / (1.f + expf(-ip));
    g_alpha[i] = a;
    g_xh2[i]   = sqrtf(1.f - a * a + 1e-6f) * si * g_xh1[i];
}

// ------------- chunked linear-recurrence scan -------------
__global__ void k_scan1()
{
    int n = blockIdx.x * blockDim.x + threadIdx.x;
    if (n >= nB * NG * nHID) return;
    int b = n / (NG * nHID);
    int r = n - b * NG * nHID;
    int g = r / nHID;
    int h = r - g * nHID;
    size_t idx = ((size_t)b * nT + (size_t)g * CH) * nHID + h;
    float A = 1.f, Bv = 0.f;
#pragma unroll 4
    for (int i = 0; i < CH; i++) {
        float a = g_alpha[idx], x = g_xh2[idx];
        Bv = a * Bv + x;
        A *= a;
        idx += nHID;
    }
    g_cA[n] = A; g_cB[n] = Bv;
}

__global__ void k_scan2()
{
    int n = blockIdx.x * blockDim.x + threadIdx.x;
    if (n >= nB * nHID) return;
    int b = n / nHID;
    int h = n - b * nHID;
    float s = 0.f;
    for (int g = 0; g < NG; g++) {
        int j = (b * NG + g) * nHID + h;
        g_carry[j] = s;
        s = g_cA[j] * s + g_cB[j];
    }
}

__global__ void k_scan3()
{
    int n = blockIdx.x * blockDim.x + threadIdx.x;
    if (n >= nB * NG * nHID) return;
    int b = n / (NG * nHID);
    int r = n - b * NG * nHID;
    int g = r / nHID;
    int h = r - g * nHID;
    size_t idx = ((size_t)b * nT + (size_t)g * CH) * nHID + h;
    float run = g_carry[n];
#pragma unroll 4
    for (int i = 0; i < CH; i++) {
        run = g_alpha[idx] * run + g_xh2[idx];
        g_hbuf[idx] = run;
        idx += nHID;
    }
}

// ------------- fused: xh3, xr, per-token qk dot (vs qw[seg]), per-token wg dot -------------
__global__ __launch_bounds__(256) void k_fuse(const float* __restrict__ wg)
{
    int m = blockIdx.x;
    int tid = threadIdx.x;
    int t = m & (nT - 1);
    int s = t >> 8;                  // t / 256
    __shared__ float r1[256], r2[256];
    float qkp = 0.f, xgp = 0.f;
    for (int h = tid; h < nHID; h += 256) {
        float gt = g_proj[(size_t)m * nHID2 + h];
        float x2 = g_xh2[(size_t)m * nHID + h];
        float hv = g_hbuf[(size_t)m * nHID + h];
        float x3 = gt * (1.f / (1.f + expf(-gt))) * x2;                     // silu(gate)*xh2
        float xrv = 0.5f * x3 * (1.f + erff(x3 * 0.7071067811865476f)) * hv; // gelu(x3)*h
        g_xh3[(size_t)m * nHID + h] = x3;
        g_xr [(size_t)m * nHID + h] = xrv;
        qkp += g_qw[s * nHID + h] * x3;
        xgp += wg[h] * xrv;
    }
    r1[tid] = qkp; r2[tid] = xgp;
    __syncthreads();
    for (int o = 128; o > 0; o >>= 1) {
        if (tid < o) { r1[tid] += r1[tid + o]; r2[tid] += r2[tid + o]; }
        __syncthreads();
    }
    if (tid == 0) { g_qk[m] = r1[0] * INV_SQRT_D; g_xg[m] = r2[0]; }
}

// ------------- per-(b,s) softmax over L=256 + weighted sum u[h] = sum_l attn*xh3 -------------
__global__ __launch_bounds__(256) void k_segsoft()
{
    int bs = blockIdx.x;            // 0..63
    int hb = blockIdx.y;            // 0..5
    int tid = threadIdx.x;
    int b = bs >> 4, s = bs & 15;
    size_t base = (size_t)b * nT + (size_t)s * nL;
    __shared__ float at[256];
    __shared__ float red[256];
    float v = g_qk[base + tid];
    red[tid] = v; __syncthreads();
    for (int o = 128; o > 0; o >>= 1) {
        if (tid < o) red[tid] = fmaxf(red[tid], red[tid + o]);
        __syncthreads();
    }
    float mx = red[0];
    __syncthreads();
    float e = expf(v - mx);
    red[tid] = e; __syncthreads();
    for (int o = 128; o > 0; o >>= 1) {
        if (tid < o) red[tid] += red[tid + o];
        __syncthreads();
    }
    at[tid] = e / red[0];
    __syncthreads();
    int h = hb * 256 + tid;
    const float* xp = g_xh3 + base * nHID + h;
    float a0 = 0.f, a1 = 0.f, a2 = 0.f, a3 = 0.f;
    for (int l = 0; l < nL; l += 4) {
        a0 += at[l + 0] * xp[(size_t)(l + 0) * nHID];
        a1 += at[l + 1] * xp[(size_t)(l + 1) * nHID];
        a2 += at[l + 2] * xp[(size_t)(l + 2) * nHID];
        a3 += at[l + 3] * xp[(size_t)(l + 3) * nHID];
    }
    g_u[(size_t)bs * nHID + h] = (a0 + a1) + (a2 + a3);
}

// ------------- mem[bs,d] = sum_h wv_w[d,h]*u[bs,h] -------------
__global__ void k_memproj(const float* __restrict__ wv)
{
    int n = blockIdx.x * blockDim.x + threadIdx.x;
    if (n >= nB * nS * nD) return;
    int bs = n / nD, d = n % nD;
    const float* up = g_u + (size_t)bs * nHID;
    const float* wp = wv + (size_t)d * nHID;
    float a = 0.f;
#pragma unroll 4
    for (int h = 0; h < nHID; h++) a += wp[h] * up[h];
    g_mem[n] = a;
}

// ------------- rk[bs,d] = sum_e mem[bs,e]*rk_w[d,e] -------------
__global__ void k_rkproj(const float* __restrict__ rkw)
{
    int n = blockIdx.x * blockDim.x + threadIdx.x;
    if (n >= nB * nS * nD) return;
    int bs = n / nD, d = n % nD;
    const float* mp = g_mem + (size_t)bs * nD;
    const float* wp = rkw + (size_t)d * nD;
    float a = 0.f;
#pragma unroll 4
    for (int e = 0; e < nD; e++) a += mp[e] * wp[e];
    g_rk[n] = a;
}

// ------------- rv[bs,h] = sum_d mem[bs,d]*rv_w[h,d] -------------
__global__ void k_rvproj(const float* __restrict__ rvw)
{
    int n = blockIdx.x * blockDim.x + threadIdx.x;
    if (n >= nB * nS * nHID) return;
    int bs = n / nHID, h = n % nHID;
    const float* mp = g_mem + (size_t)bs * nD;
    const float* wp = rvw + (size_t)h * nD;
    float a = 0.f;
#pragma unroll 4
    for (int d = 0; d < nD; d++) a += mp[d] * wp[d];
    g_rv[n] = a;
}

// ------------- per-token cross-segment attention (S=16, causal-by-segment) + gate -------------
__global__ __launch_bounds__(128) void k_attn2()
{
    int m = blockIdx.x;
    int b = m / nT, t = m % nT;
    int seg = t >> 8;
    int tid = threadIdx.x;
    __shared__ float rqs[nD];
    __shared__ float sc[nS];
    __shared__ float a2[nS];
    for (int i = tid; i < nD; i += 128) rqs[i] = g_rq[(size_t)m * nD + i];
    __syncthreads();
    int warp = tid >> 5, lane = tid & 31;
    for (int s = warp; s < nS; s += 4) {
        const float* rkp = g_rk + (size_t)(b * nS + s) * nD;
        float p = 0.f;
        for (int d = lane; d < nD; d += 32) p += rqs[d] * rkp[d];
#pragma unroll
        for (int o = 16; o > 0; o >>= 1) p += __shfl_xor_sync(0xffffffffu, p, o);
        if (lane == 0) sc[s] = p * INV_SQRT_D;
    }
    __syncthreads();
    if (tid == 0) {
        float mx = -1e30f;
        for (int s = seg; s < nS; s++) mx = fmaxf(mx, sc[s]);
        float sum = 0.f;
        for (int s = 0; s < nS; s++) {
            float e = (s >= seg) ? expf(sc[s] - mx) : 0.f;
            a2[s] = e; sum += e;
        }
        float inv = 1.f / sum;
        for (int s = 0; s < nS; s++) a2[s] *= inv;
    }
    __syncthreads();
    float gatev = 1.f / (1.f + expf(-g_xg[m]));
    for (int h = tid; h < nHID; h += 128) {
        float acc = 0.f;
#pragma unroll
        for (int s = 0; s < nS; s++) acc += a2[s] * g_rv[(size_t)(b * nS + s) * nHID + h];
        g_outg[(size_t)m * nHID + h] = gatev * acc;
    }
}

} // namespace lsgm

extern "C" void kernel_launch(void* const* d_in, const int* in_sizes, int n_in,
                              void* d_out, int out_size)
{
    using namespace lsgm;
    const float* x        = (const float*)d_in[0];
    const float* input_w  = (const float*)d_in[1];
    const float* conv_w   = (const float*)d_in[2];
    const float* conv_b   = (const float*)d_in[3];
    const float* gates_w  = (const float*)d_in[4];
    const float* gates_b  = (const float*)d_in[5];
    const float* fbase    = (const float*)d_in[6];
    const float* output_w = (const float*)d_in[7];
    const float* mslots   = (const float*)d_in[8];
    const float* wq_w     = (const float*)d_in[9];
    const float* wk_w     = (const float*)d_in[10];
    const float* wv_w     = (const float*)d_in[11];
    const float* wg_w     = (const float*)d_in[12];
    const float* rq_w     = (const float*)d_in[13];
    const float* rk_w     = (const float*)d_in[14];
    const float* rv_w     = (const float*)d_in[15];
    float* out = (float*)d_out;

    float* proj_p; cudaGetSymbolAddress((void**)&proj_p, g_proj);
    float* xh1_p;  cudaGetSymbolAddress((void**)&xh1_p,  g_xh1);
    float* gbuf_p; cudaGetSymbolAddress((void**)&gbuf_p, g_gbuf);
    float* xr_p;   cudaGetSymbolAddress((void**)&xr_p,   g_xr);
    float* rq_p;   cudaGetSymbolAddress((void**)&rq_p,   g_rq);
    float* outg_p; cudaGetSymbolAddress((void**)&outg_p, g_outg);

    // memory-slot query path (independent of x)
    k_qproj <<<(nS * nD + 255) / 256, 256>>>(mslots, wq_w);
    k_qwproj<<<(nS * nHID + 255) / 256, 256>>>(wk_w);

    // proj = x @ input_w^T  -> [M, 3072]
    sgemm_nt<<<dim3(nHID2 / 128, nM / 128), 256>>>(x, input_w, nullptr, proj_p, nM, nHID2, nDIM);

    // causal depthwise conv
    k_conv<<<(nM * nHID) / 256, 256>>>(conv_w, conv_b);

    // gates = xh1 @ gates_w^T + gates_b -> [M, 3072]
    sgemm_nt<<<dim3(nHID2 / 128, nM / 128), 256>>>(xh1_p, gates_w, gates_b, gbuf_p, nM, nHID2, nHID);

    // alpha, scan input
    k_alpha<<<(nM * nHID) / 256, 256>>>(fbase);

    // chunked scan: h[t] = alpha[t]*h[t-1] + xh2[t]
    k_scan1<<<(nB * NG * nHID) / 256, 256>>>();
    k_scan2<<<(nB * nHID) / 256, 256>>>();
    k_scan3<<<(nB * NG * nHID) / 256, 256>>>();

    // xh3, xr, qk dot, wg dot
    k_fuse<<<nM, 256>>>(wg_w);

    // slot attention over each segment, then tiny projections
    k_segsoft<<<dim3(nB * nS, nHID / 256), 256>>>();
    k_memproj<<<(nB * nS * nD) / 256, 256>>>(wv_w);
    k_rkproj <<<(nB * nS * nD) / 256, 256>>>(rk_w);
    k_rvproj <<<(nB * nS * nHID) / 256, 256>>>(rv_w);

    // rq = xr @ rq_w^T -> [M, 384]
    sgemm_nt<<<dim3(nD / 128, nM / 128), 256>>>(xr_p, rq_w, nullptr, rq_p, nM, nD, nHID);

    // cross-segment attention + output gate
    k_attn2<<<nM, 128>>>();

    // final: out = outg @ output_w^T -> [M, 1024]
    sgemm_nt<<<dim3(nDIM / 128, nM / 128), 256>>>(outg_p, output_w, nullptr, out, nM, nDIM, nHID);
}